// round 12
// baseline (speedup 1.0000x reference)
#include <cuda_runtime.h>

#define GX 1024
#define GY 1024
#define GZ 40
#define MAXV 60000
#define MAXP 32
#define SLOTS (MAXV * MAXP)
#define BLK 256
#define IPT 4
#define TILE (BLK * IPT)
#define NMAX 1250000
#define NTMAX ((NMAX + TILE - 1) / TILE + 8)
#define PV_RESOLVED 0x40000000
#define NRB 48        // non-rep blocks in kC
#define VPW 4         // voxels per warp in kD
#define VOXBLKS (MAXV / (VPW * (BLK / 32)))  // 1875
#define ZPT 4         // ulonglong2 zero-stores per thread in kD tail

// L2-resident open-addressing hash table. Entry: 0 = empty,
// else ((flat+1) << 21) | key, key = n - i (n < 2^21). Cell ownership is
// set-once (CAS from 0); all same-flat contenders then share high bits so
// atomicMax == per-voxel first-point claim. Each flat resolves to exactly one
// slot. Zeroed in kD's tail blocks each call (runs in kD's latency shadow).
#define HBITS 21
#define HSIZE (1u << HBITS)
#define HMASK (HSIZE - 1u)
#define KMASK 0x1FFFFFull

__device__ __align__(16) unsigned long long g_htab[HSIZE];
__device__ int      g_sidx[NMAX];     // resolved hash slot per point, -1 invalid
__device__ int      g_pvid[NMAX];     // reps: PV_RESOLVED|vid (others stale, never read)
__device__ unsigned long long g_nrList[NMAX];  // non-reps: (i << 21) | i_rep
__device__ int      g_nrCount;        // reset by kD
__device__ unsigned g_status[NTMAX];  // lookback: 0 | 0x4000_0000|agg | 0x8000_0000|incl
__device__ int      g_voxelNum;
__device__ unsigned g_slots[SLOTS];   // keys; only touched slots reset by kD
__device__ int      g_cnt[MAXV];      // reset by kD
__device__ int      g_coors[MAXV * 3];

__device__ __forceinline__ unsigned hslot(int flat) {
    return (unsigned)(((unsigned long long)(unsigned)flat * 0x9E3779B97F4A7C15ull) >> (64 - HBITS));
}

// ---------------------------------------------------------------------------
// A: 4 consecutive points per thread. First CAS of each point is hoisted and
// batch-issued (MLP 4, one latency wait); only the rare conflict path (~2%)
// enters the per-point resolve loop. Value-identical to the R10/R11 protocol.
// ---------------------------------------------------------------------------
__global__ void kA_claim(const float4* __restrict__ pts, int n) {
    int t = blockIdx.x * BLK + threadIdx.x;
    int i0 = t * IPT;

    int fl[IPT];
    unsigned sv[IPT];
    unsigned long long ent[IPT];
    #pragma unroll
    for (int k = 0; k < IPT; k++) {
        int i = i0 + k;
        fl[k] = -1;
        if (i < n) {
            float4 p = pts[i];
            // exact mirror of reference f32 math: floor((p - rmin) / vs)
            int cx = (int)floorf((p.x - (-51.2f)) / 0.1f);
            int cy = (int)floorf((p.y - (-51.2f)) / 0.1f);
            int cz = (int)floorf((p.z - (-5.0f)) / 0.2f);
            if ((unsigned)cx < GX && (unsigned)cy < GY && (unsigned)cz < GZ) {
                int flat = (cx * GY + cy) * GZ + cz;
                fl[k] = flat;
                sv[k] = hslot(flat);
                ent[k] = (((unsigned long long)(unsigned)(flat + 1)) << 21)
                       | (unsigned)(n - i);
            }
        }
    }

    // batch-issue the first CAS for all 4 points (independent -> MLP 4)
    unsigned long long old0[IPT];
    #pragma unroll
    for (int k = 0; k < IPT; k++)
        if (fl[k] >= 0) old0[k] = atomicCAS(&g_htab[sv[k]], 0ull, ent[k]);

    // resolve (fast path: old0 == 0 claimed, or same-flat -> conditional max)
    int sres[IPT];
    #pragma unroll
    for (int k = 0; k < IPT; k++) {
        if (fl[k] < 0) { sres[k] = -1; continue; }
        unsigned long long fp1 = (unsigned long long)(unsigned)(fl[k] + 1);
        unsigned key = (unsigned)(ent[k] & KMASK);
        unsigned s = sv[k];
        unsigned long long old = old0[k];
        for (;;) {
            if (old == 0ull) break;                       // claimed empty slot
            if ((old >> 21) == fp1) {                     // our voxel's slot
                if ((unsigned)(old & KMASK) < key) atomicMax(&g_htab[s], ent[k]);
                break;
            }
            s = (s + 1) & HMASK;                          // other flat: probe on
            old = atomicCAS(&g_htab[s], 0ull, ent[k]);
        }
        sres[k] = (int)s;
    }

    if (i0 + IPT <= n) {
        *reinterpret_cast<int4*>(&g_sidx[i0]) = make_int4(sres[0], sres[1], sres[2], sres[3]);
    } else {
        for (int k = 0; k < IPT; k++)
            if (i0 + k < n) g_sidx[i0 + k] = sres[k];
    }
}

// ---------------------------------------------------------------------------
// B: entry gather -> rep flags -> block scan + decoupled lookback -> vid.
// Reps write pvid, and (vid<MAXV) coors + slot0 key + cnt=1 + the OUTPUT row
// (slot 0 is always the rep: ripple keys are descending).
// Non-reps (~0.5%) warp-aggregate into a compact list (ONE atomic per warp).
// ---------------------------------------------------------------------------
__global__ void kB_scan_assign(const float4* __restrict__ pts, float* __restrict__ out,
                               int n, int nTiles) {
    const int tid = threadIdx.x;
    const int lane = tid & 31, wid = tid >> 5;
    const int tile = blockIdx.x;
    const int i0 = (tile * BLK + tid) * IPT;

    __shared__ int s_warp[BLK / 32];
    __shared__ int s_incl[BLK / 32];
    __shared__ int s_run;
    __shared__ int s_excl;

    // front-batched loads: sidx (int4), entry gathers (L2-resident table)
    int sidx[IPT];
    if (i0 + IPT <= n) {
        int4 s4 = *reinterpret_cast<const int4*>(&g_sidx[i0]);
        sidx[0] = s4.x; sidx[1] = s4.y; sidx[2] = s4.z; sidx[3] = s4.w;
    } else {
        #pragma unroll
        for (int k = 0; k < IPT; k++)
            sidx[k] = (i0 + k < n) ? g_sidx[i0 + k] : -1;
    }
    unsigned long long cell[IPT];
    #pragma unroll
    for (int k = 0; k < IPT; k++)
        cell[k] = (sidx[k] >= 0) ? __ldcg(&g_htab[sidx[k]]) : 0ull;

    int flat[IPT], key[IPT], rep[IPT];
    int c = 0;
    #pragma unroll
    for (int k = 0; k < IPT; k++) {
        flat[k] = (int)(cell[k] >> 21) - 1;
        key[k] = (int)(cell[k] & KMASK);          // n - i_rep
        rep[k] = (sidx[k] >= 0 && key[k] == n - (i0 + k)) ? 1 : 0;
        c += rep[k];
    }

    // single block exclusive scan of per-thread counts (point order == tid,k order)
    int v = c;
    #pragma unroll
    for (int o = 1; o < 32; o <<= 1) {
        int tv = __shfl_up_sync(0xffffffffu, v, o);
        if (lane >= o) v += tv;
    }
    if (lane == 31) s_warp[wid] = v;
    __syncthreads();
    if (tid < BLK / 32) {
        int w = s_warp[tid];
        #pragma unroll
        for (int o = 1; o < BLK / 32; o <<= 1) {
            int tv = __shfl_up_sync(0xffu, w, o);
            if (tid >= o) w += tv;
        }
        s_incl[tid] = w;
        if (tid == BLK / 32 - 1) s_run = w;
    }
    __syncthreads();
    int thrExcl = (wid ? s_incl[wid - 1] : 0) + (v - c);
    int agg = s_run;

    // publish aggregate, warp-parallel lookback (volatile — proven R4-R11)
    volatile unsigned* vst = g_status;
    if (wid == 0) {
        if (lane == 0) vst[tile] = 0x40000000u | (unsigned)agg;
        unsigned excl = 0;
        int j = tile - 1;
        while (j >= 0) {
            int idx = j - lane;
            unsigned w;
            if (idx >= 0) {
                do { w = vst[idx]; } while (w == 0u);
            } else {
                w = 0x80000000u;  // virtual prefix 0 before tile 0
            }
            unsigned isPre = __ballot_sync(0xffffffffu, (w & 0x80000000u) != 0u);
            if (isPre) {
                int pl = __ffs(isPre) - 1;
                unsigned contrib = (lane <= pl) ? (w & 0x3FFFFFFFu) : 0u;
                #pragma unroll
                for (int o = 16; o; o >>= 1) contrib += __shfl_down_sync(0xffffffffu, contrib, o);
                if (lane == 0) excl += contrib;
                break;
            } else {
                unsigned contrib = w & 0x3FFFFFFFu;
                #pragma unroll
                for (int o = 16; o; o >>= 1) contrib += __shfl_down_sync(0xffffffffu, contrib, o);
                if (lane == 0) excl += contrib;
                j -= 32;
            }
        }
        if (lane == 0) {
            s_excl = (int)excl;
            vst[tile] = 0x80000000u | (excl + (unsigned)agg);
            if (tile == nTiles - 1) {
                int tot = (int)(excl + (unsigned)agg);
                g_voxelNum = tot < MAXV ? tot : MAXV;
            }
        }
    }
    __syncthreads();
    int base = s_excl + thrExcl;

    // phase 3a: reps emit (incl. the output row)
    int running = 0;
    bool isNR[IPT];
    #pragma unroll
    for (int k = 0; k < IPT; k++) {
        int i = i0 + k;
        bool valid = (i < n) && (sidx[k] >= 0);
        isNR[k] = valid && !rep[k];
        if (valid && rep[k]) {
            int vid = base + running;
            running++;
            g_pvid[i] = PV_RESOLVED | vid;
            if (vid < MAXV) {
                int f = flat[k];
                g_coors[vid * 3 + 0] = f % GZ;
                g_coors[vid * 3 + 1] = (f / GZ) % GY;
                g_coors[vid * 3 + 2] = f / (GZ * GY);
                g_slots[vid * MAXP] = (unsigned)(n - i);  // rep key guards slot 0
                g_cnt[vid] = 1;
                reinterpret_cast<float4*>(out)[vid * MAXP] = pts[i];  // slot 0 = rep, final
            }
        }
    }

    // phase 3b: non-rep append, ONE atomicAdd per warp (list order irrelevant:
    // ripple final-state is insertion-order independent)
    unsigned m[IPT];
    int warpTot = 0;
    #pragma unroll
    for (int k = 0; k < IPT; k++) {
        m[k] = __ballot_sync(0xffffffffu, isNR[k]);
        warpTot += __popc(m[k]);
    }
    if (warpTot) {
        int wb;
        if (lane == 0) wb = atomicAdd(&g_nrCount, warpTot);
        wb = __shfl_sync(0xffffffffu, wb, 0);
        int off = 0;
        #pragma unroll
        for (int k = 0; k < IPT; k++) {
            if (isNR[k]) {
                int pre = off + __popc(m[k] & ((1u << lane) - 1u));
                int i = i0 + k;
                g_nrList[wb + pre] =
                    ((unsigned long long)(unsigned)i << 21) | (unsigned)(n - key[k]);
            }
            off += __popc(m[k]);
        }
    }
}

// ---------------------------------------------------------------------------
// C: micro-kernel — non-rep inserts only (rep vid lookup + count +
// deterministic atomicMax ripple; rep key in slot 0 pushes them to slot 1+).
// ---------------------------------------------------------------------------
__global__ void kC_nonrep(int n) {
    int total = g_nrCount;
    for (int j = blockIdx.x * BLK + threadIdx.x; j < total; j += NRB * BLK) {
        unsigned long long e = g_nrList[j];
        int i = (int)(e >> 21);
        int irep = (int)(e & KMASK);
        int vid = __ldcg(&g_pvid[irep]) & (PV_RESOLVED - 1);
        if (vid >= MAXV) continue;
        atomicAdd(&g_cnt[vid], 1);
        unsigned key = (unsigned)(n - i);
        unsigned* sl = &g_slots[(unsigned)vid * MAXP];
        for (int s = 0; s < MAXP; s++) {
            unsigned old = atomicMax(&sl[s], key);
            if (old < key) {
                if (old == 0u) break;  // landed in empty slot
                key = old;             // displaced occupant ripples right
            }
        }
    }
}

// ---------------------------------------------------------------------------
// D: split grid. Head: 4 voxels per warp emit [proven R9-R11]. Tail: htab
// stream-zero (4 x 16B per thread) + status clear, in the emit's latency
// shadow.
// Output layout: voxels[60000*32*4] | coors[60000*3] | npv[60000] | voxel_num[1]
// ---------------------------------------------------------------------------
__global__ void kD_emit(const float4* __restrict__ pts, float* __restrict__ out,
                        int n, int nTiles) {
    int b = blockIdx.x;
    if (b < VOXBLKS) {
        int lane = threadIdx.x & 31;
        int vbase = ((b * BLK + threadIdx.x) >> 5) * VPW;
        const int OC = SLOTS * 4;
        const int ON = OC + MAXV * 3;
        int vn = g_voxelNum;

        int c = 0;
        if (lane < VPW) c = g_cnt[vbase + lane];
        if (lane < 3 * VPW) {
            int coor = g_coors[vbase * 3 + lane];
            out[OC + vbase * 3 + lane] = (vbase + lane / 3 < vn) ? (float)coor : 0.f;
        }
        if (lane < VPW) {
            if (c) g_cnt[vbase + lane] = 0;
            out[ON + vbase + lane] = (float)(c > MAXP ? MAXP : c);
        }
        if (b == 0 && threadIdx.x == 0) {
            out[ON + MAXV] = (float)vn;
            g_nrCount = 0;
        }

        const float4 zero = make_float4(0.f, 0.f, 0.f, 0.f);
        #pragma unroll
        for (int j = 0; j < VPW; j++) {
            int cj = __shfl_sync(0xffffffffu, c, j);
            int row = (vbase + j) * MAXP + lane;
            if (cj <= 1) {
                if (lane || cj == 0) reinterpret_cast<float4*>(out)[row] = zero;
                if (cj == 1 && lane == 0) g_slots[row] = 0;
            } else {
                unsigned k = g_slots[row];
                g_slots[row] = 0;
                if (lane)  // lane 0's row written by kB (slot 0 == rep, final)
                    reinterpret_cast<float4*>(out)[row] = k ? pts[n - (int)k] : zero;
            }
        }
    } else {
        int tb = b - VOXBLKS;
        const int ZTHREADS = (int)(HSIZE / 2) / ZPT;   // threads needed for zeroing
        int j = tb * BLK + threadIdx.x;
        if (j < ZTHREADS) {
            ulonglong2* dst = reinterpret_cast<ulonglong2*>(g_htab) + (size_t)j * ZPT;
            #pragma unroll
            for (int q = 0; q < ZPT; q++) dst[q] = make_ulonglong2(0ull, 0ull);
        } else {
            int j2 = j - ZTHREADS;
            if (j2 < nTiles) g_status[j2] = 0;
        }
    }
}

extern "C" void kernel_launch(void* const* d_in, const int* in_sizes, int n_in,
                              void* d_out, int out_size) {
    const float4* pts = (const float4*)d_in[0];
    int n = in_sizes[0] / 4;
    float* out = (float*)d_out;
    int nT = (n + TILE - 1) / TILE;

    kA_claim<<<nT, BLK>>>(pts, n);
    kB_scan_assign<<<nT, BLK>>>(pts, out, n, nT);
    kC_nonrep<<<NRB, BLK>>>(n);
    int tailBlocks = ((int)(HSIZE / 2) / ZPT + nT + BLK - 1) / BLK;
    kD_emit<<<VOXBLKS + tailBlocks, BLK>>>(pts, out, n, nT);
}

// round 13
// speedup vs baseline: 1.0941x; 1.0941x over previous
#include <cuda_runtime.h>

#define GX 1024
#define GY 1024
#define GZ 40
#define MAXV 60000
#define MAXP 32
#define SLOTS (MAXV * MAXP)
#define BLK 256
#define IPT 4
#define TILE (BLK * IPT)
#define NMAX 1250000
#define NTMAX ((NMAX + TILE - 1) / TILE + 8)
#define PV_RESOLVED 0x40000000
#define NRB 48        // non-rep blocks in kC
#define VPW 4         // voxels per warp in kD
#define VOXBLKS (MAXV / (VPW * (BLK / 32)))  // 1875

// L2-resident open-addressing hash table. Entry: 0 = empty,
// else ((flat+1) << 21) | key, key = n - i (n < 2^21). Cell ownership is
// set-once (CAS from 0); all same-flat contenders then share high bits so
// atomicMax == per-voxel first-point claim. Each flat resolves to exactly one
// slot. Zeroed in kD's tail blocks each call (runs in kD's latency shadow).
#define HBITS 21
#define HSIZE (1u << HBITS)
#define HMASK (HSIZE - 1u)
#define KMASK 0x1FFFFFull

__device__ __align__(16) unsigned long long g_htab[HSIZE];
__device__ int      g_sidx[NMAX];     // resolved hash slot per point, -1 invalid
__device__ int      g_pvid[NMAX];     // reps: PV_RESOLVED|vid (others stale, never read)
__device__ unsigned long long g_nrList[NMAX];  // non-reps: (i << 21) | i_rep
__device__ int      g_nrCount;        // reset by kD
__device__ unsigned g_status[NTMAX];  // lookback: 0 | 0x4000_0000|agg | 0x8000_0000|incl
__device__ int      g_voxelNum;
__device__ unsigned g_slots[SLOTS];   // keys; only touched slots reset by kD
__device__ int      g_cnt[MAXV];      // reset by kD

__device__ __forceinline__ unsigned hslot(int flat) {
    return (unsigned)(((unsigned long long)(unsigned)flat * 0x9E3779B97F4A7C15ull) >> (64 - HBITS));
}

// ---------------------------------------------------------------------------
// A: 4 consecutive points per thread; coords -> CAS-first hash claim; cache
// resolved slot index (int4 store).  [R11 version — measured best]
// ---------------------------------------------------------------------------
__global__ void kA_claim(const float4* __restrict__ pts, int n) {
    int t = blockIdx.x * BLK + threadIdx.x;
    int i0 = t * IPT;
    int sres[IPT];
    #pragma unroll
    for (int k = 0; k < IPT; k++) {
        int i = i0 + k;
        int sidx = -1;
        if (i < n) {
            float4 p = pts[i];
            // exact mirror of reference f32 math: floor((p - rmin) / vs)
            int cx = (int)floorf((p.x - (-51.2f)) / 0.1f);
            int cy = (int)floorf((p.y - (-51.2f)) / 0.1f);
            int cz = (int)floorf((p.z - (-5.0f)) / 0.2f);
            if ((unsigned)cx < GX && (unsigned)cy < GY && (unsigned)cz < GZ) {
                int flat = (cx * GY + cy) * GZ + cz;
                unsigned long long fp1 = (unsigned long long)(unsigned)(flat + 1);
                unsigned key = (unsigned)(n - i);
                unsigned long long ent = (fp1 << 21) | key;
                unsigned s = hslot(flat);
                for (;;) {
                    unsigned long long old = atomicCAS(&g_htab[s], 0ull, ent);
                    if (old == 0ull) break;                       // claimed empty slot
                    if ((old >> 21) == fp1) {                     // our voxel's slot
                        if ((unsigned)(old & KMASK) < key) atomicMax(&g_htab[s], ent);
                        break;
                    }
                    s = (s + 1) & HMASK;                          // other flat: probe on
                }
                sidx = (int)s;
            }
        }
        sres[k] = sidx;
    }
    if (i0 + IPT <= n) {
        *reinterpret_cast<int4*>(&g_sidx[i0]) = make_int4(sres[0], sres[1], sres[2], sres[3]);
    } else {
        for (int k = 0; k < IPT; k++)
            if (i0 + k < n) g_sidx[i0 + k] = sres[k];
    }
}

// ---------------------------------------------------------------------------
// B: entry gather -> rep flags -> block scan + decoupled lookback -> vid.
// Reps write pvid, and (vid<MAXV) coors DIRECTLY INTO OUT (vid<MAXV implies
// vid<voxelNum, so the row is final) + slot0 key + cnt=1 + the OUTPUT row
// (slot 0 is always the rep: ripple keys are descending).
// Non-reps (~0.5%) warp-aggregate into a compact list (ONE atomic per warp).
// ---------------------------------------------------------------------------
__global__ void kB_scan_assign(const float4* __restrict__ pts, float* __restrict__ out,
                               int n, int nTiles) {
    const int tid = threadIdx.x;
    const int lane = tid & 31, wid = tid >> 5;
    const int tile = blockIdx.x;
    const int i0 = (tile * BLK + tid) * IPT;

    __shared__ int s_warp[BLK / 32];
    __shared__ int s_incl[BLK / 32];
    __shared__ int s_run;
    __shared__ int s_excl;

    // front-batched loads: sidx (int4), entry gathers (L2-resident table)
    int sidx[IPT];
    if (i0 + IPT <= n) {
        int4 s4 = *reinterpret_cast<const int4*>(&g_sidx[i0]);
        sidx[0] = s4.x; sidx[1] = s4.y; sidx[2] = s4.z; sidx[3] = s4.w;
    } else {
        #pragma unroll
        for (int k = 0; k < IPT; k++)
            sidx[k] = (i0 + k < n) ? g_sidx[i0 + k] : -1;
    }
    unsigned long long cell[IPT];
    #pragma unroll
    for (int k = 0; k < IPT; k++)
        cell[k] = (sidx[k] >= 0) ? __ldcg(&g_htab[sidx[k]]) : 0ull;

    int flat[IPT], key[IPT], rep[IPT];
    int c = 0;
    #pragma unroll
    for (int k = 0; k < IPT; k++) {
        flat[k] = (int)(cell[k] >> 21) - 1;
        key[k] = (int)(cell[k] & KMASK);          // n - i_rep
        rep[k] = (sidx[k] >= 0 && key[k] == n - (i0 + k)) ? 1 : 0;
        c += rep[k];
    }

    // single block exclusive scan of per-thread counts (point order == tid,k order)
    int v = c;
    #pragma unroll
    for (int o = 1; o < 32; o <<= 1) {
        int tv = __shfl_up_sync(0xffffffffu, v, o);
        if (lane >= o) v += tv;
    }
    if (lane == 31) s_warp[wid] = v;
    __syncthreads();
    if (tid < BLK / 32) {
        int w = s_warp[tid];
        #pragma unroll
        for (int o = 1; o < BLK / 32; o <<= 1) {
            int tv = __shfl_up_sync(0xffu, w, o);
            if (tid >= o) w += tv;
        }
        s_incl[tid] = w;
        if (tid == BLK / 32 - 1) s_run = w;
    }
    __syncthreads();
    int thrExcl = (wid ? s_incl[wid - 1] : 0) + (v - c);
    int agg = s_run;

    // publish aggregate, warp-parallel lookback (volatile — proven R4-R12)
    volatile unsigned* vst = g_status;
    if (wid == 0) {
        if (lane == 0) vst[tile] = 0x40000000u | (unsigned)agg;
        unsigned excl = 0;
        int j = tile - 1;
        while (j >= 0) {
            int idx = j - lane;
            unsigned w;
            if (idx >= 0) {
                do { w = vst[idx]; } while (w == 0u);
            } else {
                w = 0x80000000u;  // virtual prefix 0 before tile 0
            }
            unsigned isPre = __ballot_sync(0xffffffffu, (w & 0x80000000u) != 0u);
            if (isPre) {
                int pl = __ffs(isPre) - 1;
                unsigned contrib = (lane <= pl) ? (w & 0x3FFFFFFFu) : 0u;
                #pragma unroll
                for (int o = 16; o; o >>= 1) contrib += __shfl_down_sync(0xffffffffu, contrib, o);
                if (lane == 0) excl += contrib;
                break;
            } else {
                unsigned contrib = w & 0x3FFFFFFFu;
                #pragma unroll
                for (int o = 16; o; o >>= 1) contrib += __shfl_down_sync(0xffffffffu, contrib, o);
                if (lane == 0) excl += contrib;
                j -= 32;
            }
        }
        if (lane == 0) {
            s_excl = (int)excl;
            vst[tile] = 0x80000000u | (excl + (unsigned)agg);
            if (tile == nTiles - 1) {
                int tot = (int)(excl + (unsigned)agg);
                g_voxelNum = tot < MAXV ? tot : MAXV;
            }
        }
    }
    __syncthreads();
    int base = s_excl + thrExcl;

    // phase 3a: reps emit (incl. the output voxel row AND output coors row)
    const int OC = SLOTS * 4;
    int running = 0;
    bool isNR[IPT];
    #pragma unroll
    for (int k = 0; k < IPT; k++) {
        int i = i0 + k;
        bool valid = (i < n) && (sidx[k] >= 0);
        isNR[k] = valid && !rep[k];
        if (valid && rep[k]) {
            int vid = base + running;
            running++;
            g_pvid[i] = PV_RESOLVED | vid;
            if (vid < MAXV) {
                int f = flat[k];
                out[OC + vid * 3 + 0] = (float)(f % GZ);
                out[OC + vid * 3 + 1] = (float)((f / GZ) % GY);
                out[OC + vid * 3 + 2] = (float)(f / (GZ * GY));
                g_slots[vid * MAXP] = (unsigned)(n - i);  // rep key guards slot 0
                g_cnt[vid] = 1;
                reinterpret_cast<float4*>(out)[vid * MAXP] = pts[i];  // slot 0 = rep, final
            }
        }
    }

    // phase 3b: non-rep append, ONE atomicAdd per warp (list order irrelevant:
    // ripple final-state is insertion-order independent)
    unsigned m[IPT];
    int warpTot = 0;
    #pragma unroll
    for (int k = 0; k < IPT; k++) {
        m[k] = __ballot_sync(0xffffffffu, isNR[k]);
        warpTot += __popc(m[k]);
    }
    if (warpTot) {
        int wb;
        if (lane == 0) wb = atomicAdd(&g_nrCount, warpTot);
        wb = __shfl_sync(0xffffffffu, wb, 0);
        int off = 0;
        #pragma unroll
        for (int k = 0; k < IPT; k++) {
            if (isNR[k]) {
                int pre = off + __popc(m[k] & ((1u << lane) - 1u));
                int i = i0 + k;
                g_nrList[wb + pre] =
                    ((unsigned long long)(unsigned)i << 21) | (unsigned)(n - key[k]);
            }
            off += __popc(m[k]);
        }
    }
}

// ---------------------------------------------------------------------------
// C: micro-kernel — non-rep inserts only (rep vid lookup + count +
// deterministic atomicMax ripple; rep key in slot 0 pushes them to slot 1+).
// ---------------------------------------------------------------------------
__global__ void kC_nonrep(int n) {
    int total = g_nrCount;
    for (int j = blockIdx.x * BLK + threadIdx.x; j < total; j += NRB * BLK) {
        unsigned long long e = g_nrList[j];
        int i = (int)(e >> 21);
        int irep = (int)(e & KMASK);
        int vid = __ldcg(&g_pvid[irep]) & (PV_RESOLVED - 1);
        if (vid >= MAXV) continue;
        atomicAdd(&g_cnt[vid], 1);
        unsigned key = (unsigned)(n - i);
        unsigned* sl = &g_slots[(unsigned)vid * MAXP];
        for (int s = 0; s < MAXP; s++) {
            unsigned old = atomicMax(&sl[s], key);
            if (old < key) {
                if (old == 0u) break;  // landed in empty slot
                key = old;             // displaced occupant ripples right
            }
        }
    }
}

// ---------------------------------------------------------------------------
// D: split grid. Head: 4 voxels per warp emit [proven R9-R11]. Coors rows
// already written by kB for vid<vn; zero-fill only vid>=vn. Tail: htab
// stream-zero (one 16B store per thread — R11 version) + status clear.
// Output layout: voxels[60000*32*4] | coors[60000*3] | npv[60000] | voxel_num[1]
// ---------------------------------------------------------------------------
__global__ void kD_emit(const float4* __restrict__ pts, float* __restrict__ out,
                        int n, int nTiles) {
    int b = blockIdx.x;
    if (b < VOXBLKS) {
        int lane = threadIdx.x & 31;
        int vbase = ((b * BLK + threadIdx.x) >> 5) * VPW;
        const int OC = SLOTS * 4;
        const int ON = OC + MAXV * 3;
        int vn = g_voxelNum;

        int c = 0;
        if (lane < VPW) c = g_cnt[vbase + lane];
        if (lane < 3 * VPW) {
            if (vbase + lane / 3 >= vn) out[OC + vbase * 3 + lane] = 0.f;
        }
        if (lane < VPW) {
            if (c) g_cnt[vbase + lane] = 0;
            out[ON + vbase + lane] = (float)(c > MAXP ? MAXP : c);
        }
        if (b == 0 && threadIdx.x == 0) {
            out[ON + MAXV] = (float)vn;
            g_nrCount = 0;
        }

        const float4 zero = make_float4(0.f, 0.f, 0.f, 0.f);
        #pragma unroll
        for (int j = 0; j < VPW; j++) {
            int cj = __shfl_sync(0xffffffffu, c, j);
            int row = (vbase + j) * MAXP + lane;
            if (cj <= 1) {
                if (lane || cj == 0) reinterpret_cast<float4*>(out)[row] = zero;
                if (cj == 1 && lane == 0) g_slots[row] = 0;
            } else {
                unsigned k = g_slots[row];
                g_slots[row] = 0;
                if (lane)  // lane 0's row written by kB (slot 0 == rep, final)
                    reinterpret_cast<float4*>(out)[row] = k ? pts[n - (int)k] : zero;
            }
        }
    } else {
        int j = (b - VOXBLKS) * BLK + threadIdx.x;
        if (j < (int)(HSIZE / 2)) {
            // coalesced 16B stores: zero two hash entries per thread
            reinterpret_cast<ulonglong2*>(g_htab)[j] = make_ulonglong2(0ull, 0ull);
        } else {
            int j2 = j - (int)(HSIZE / 2);
            if (j2 < nTiles) g_status[j2] = 0;
        }
    }
}

extern "C" void kernel_launch(void* const* d_in, const int* in_sizes, int n_in,
                              void* d_out, int out_size) {
    const float4* pts = (const float4*)d_in[0];
    int n = in_sizes[0] / 4;
    float* out = (float*)d_out;
    int nT = (n + TILE - 1) / TILE;

    kA_claim<<<nT, BLK>>>(pts, n);
    kB_scan_assign<<<nT, BLK>>>(pts, out, n, nT);
    kC_nonrep<<<NRB, BLK>>>(n);
    int tailBlocks = ((int)(HSIZE / 2) + nT + BLK - 1) / BLK;
    kD_emit<<<VOXBLKS + tailBlocks, BLK>>>(pts, out, n, nT);
}

// round 14
// speedup vs baseline: 1.1272x; 1.0302x over previous
#include <cuda_runtime.h>

#define GX 1024
#define GY 1024
#define GZ 40
#define MAXV 60000
#define MAXP 32
#define SLOTS (MAXV * MAXP)
#define BLK 256
#define IPT 4
#define TILE (BLK * IPT)
#define NMAX 1250000
#define NTMAX ((NMAX + TILE - 1) / TILE + 8)
#define PV_RESOLVED 0x40000000
#define NRB 48        // non-rep blocks in kC
#define VPW 4         // voxels per warp in kD
#define VOXBLKS (MAXV / (VPW * (BLK / 32)))  // 1875

// L2-resident open-addressing hash table. Entry: 0 = empty,
// else ((flat+1) << 21) | key, key = n - i (n < 2^21). Cell ownership is
// set-once (CAS from 0); all same-flat contenders then share high bits so
// atomicMax == per-voxel first-point claim. Each flat resolves to exactly one
// slot. Zeroed in kD's tail blocks each call (runs in kD's latency shadow).
#define HBITS 21
#define HSIZE (1u << HBITS)
#define HMASK (HSIZE - 1u)
#define KMASK 0x1FFFFFull

__device__ __align__(16) unsigned long long g_htab[HSIZE];
__device__ int      g_sidx[NMAX];     // resolved hash slot per point, -1 invalid
__device__ int      g_pvid[NMAX];     // reps: PV_RESOLVED|vid (others stale, never read)
__device__ unsigned long long g_nrList[NMAX];  // non-reps: (i << 21) | i_rep
__device__ int      g_nrCount;        // reset by kD
__device__ unsigned g_status[NTMAX];  // lookback: 0 | 0x4000_0000|agg | 0x8000_0000|incl
__device__ int      g_voxelNum;
__device__ unsigned g_slots[SLOTS];   // keys; only touched slots reset by kD
__device__ int      g_cnt[MAXV];      // EXTRA count beyond the rep (kC only); reset by kD
__device__ int4     g_coors4[MAXV];   // (z, y, x, pad) per voxel

__device__ __forceinline__ unsigned hslot(int flat) {
    return (unsigned)(((unsigned long long)(unsigned)flat * 0x9E3779B97F4A7C15ull) >> (64 - HBITS));
}

// ---------------------------------------------------------------------------
// A: 4 consecutive points per thread; coords -> CAS-first hash claim; cache
// resolved slot index (int4 store).  [R11 version — measured best]
// ---------------------------------------------------------------------------
__global__ void kA_claim(const float4* __restrict__ pts, int n) {
    int t = blockIdx.x * BLK + threadIdx.x;
    int i0 = t * IPT;
    int sres[IPT];
    #pragma unroll
    for (int k = 0; k < IPT; k++) {
        int i = i0 + k;
        int sidx = -1;
        if (i < n) {
            float4 p = pts[i];
            // exact mirror of reference f32 math: floor((p - rmin) / vs)
            int cx = (int)floorf((p.x - (-51.2f)) / 0.1f);
            int cy = (int)floorf((p.y - (-51.2f)) / 0.1f);
            int cz = (int)floorf((p.z - (-5.0f)) / 0.2f);
            if ((unsigned)cx < GX && (unsigned)cy < GY && (unsigned)cz < GZ) {
                int flat = (cx * GY + cy) * GZ + cz;
                unsigned long long fp1 = (unsigned long long)(unsigned)(flat + 1);
                unsigned key = (unsigned)(n - i);
                unsigned long long ent = (fp1 << 21) | key;
                unsigned s = hslot(flat);
                for (;;) {
                    unsigned long long old = atomicCAS(&g_htab[s], 0ull, ent);
                    if (old == 0ull) break;                       // claimed empty slot
                    if ((old >> 21) == fp1) {                     // our voxel's slot
                        if ((unsigned)(old & KMASK) < key) atomicMax(&g_htab[s], ent);
                        break;
                    }
                    s = (s + 1) & HMASK;                          // other flat: probe on
                }
                sidx = (int)s;
            }
        }
        sres[k] = sidx;
    }
    if (i0 + IPT <= n) {
        *reinterpret_cast<int4*>(&g_sidx[i0]) = make_int4(sres[0], sres[1], sres[2], sres[3]);
    } else {
        for (int k = 0; k < IPT; k++)
            if (i0 + k < n) g_sidx[i0 + k] = sres[k];
    }
}

// ---------------------------------------------------------------------------
// B: entry gather -> rep flags -> block scan + decoupled lookback -> vid.
// Reps write pvid, and (vid<MAXV) coors (ONE int4 store) + slot0 key + the
// OUTPUT row (slot 0 is always the rep: ripple keys are descending).
// NO cnt store: kD infers the rep's 1 from vid<voxelNum.
// Non-reps (~0.5%) warp-aggregate into a compact list (ONE atomic per warp).
// ---------------------------------------------------------------------------
__global__ void kB_scan_assign(const float4* __restrict__ pts, float* __restrict__ out,
                               int n, int nTiles) {
    const int tid = threadIdx.x;
    const int lane = tid & 31, wid = tid >> 5;
    const int tile = blockIdx.x;
    const int i0 = (tile * BLK + tid) * IPT;

    __shared__ int s_warp[BLK / 32];
    __shared__ int s_incl[BLK / 32];
    __shared__ int s_run;
    __shared__ int s_excl;

    // front-batched loads: sidx (int4), entry gathers (L2-resident table)
    int sidx[IPT];
    if (i0 + IPT <= n) {
        int4 s4 = *reinterpret_cast<const int4*>(&g_sidx[i0]);
        sidx[0] = s4.x; sidx[1] = s4.y; sidx[2] = s4.z; sidx[3] = s4.w;
    } else {
        #pragma unroll
        for (int k = 0; k < IPT; k++)
            sidx[k] = (i0 + k < n) ? g_sidx[i0 + k] : -1;
    }
    unsigned long long cell[IPT];
    #pragma unroll
    for (int k = 0; k < IPT; k++)
        cell[k] = (sidx[k] >= 0) ? __ldcg(&g_htab[sidx[k]]) : 0ull;

    int flat[IPT], key[IPT], rep[IPT];
    int c = 0;
    #pragma unroll
    for (int k = 0; k < IPT; k++) {
        flat[k] = (int)(cell[k] >> 21) - 1;
        key[k] = (int)(cell[k] & KMASK);          // n - i_rep
        rep[k] = (sidx[k] >= 0 && key[k] == n - (i0 + k)) ? 1 : 0;
        c += rep[k];
    }

    // single block exclusive scan of per-thread counts (point order == tid,k order)
    int v = c;
    #pragma unroll
    for (int o = 1; o < 32; o <<= 1) {
        int tv = __shfl_up_sync(0xffffffffu, v, o);
        if (lane >= o) v += tv;
    }
    if (lane == 31) s_warp[wid] = v;
    __syncthreads();
    if (tid < BLK / 32) {
        int w = s_warp[tid];
        #pragma unroll
        for (int o = 1; o < BLK / 32; o <<= 1) {
            int tv = __shfl_up_sync(0xffu, w, o);
            if (tid >= o) w += tv;
        }
        s_incl[tid] = w;
        if (tid == BLK / 32 - 1) s_run = w;
    }
    __syncthreads();
    int thrExcl = (wid ? s_incl[wid - 1] : 0) + (v - c);
    int agg = s_run;

    // publish aggregate, warp-parallel lookback (volatile — proven R4-R13)
    volatile unsigned* vst = g_status;
    if (wid == 0) {
        if (lane == 0) vst[tile] = 0x40000000u | (unsigned)agg;
        unsigned excl = 0;
        int j = tile - 1;
        while (j >= 0) {
            int idx = j - lane;
            unsigned w;
            if (idx >= 0) {
                do { w = vst[idx]; } while (w == 0u);
            } else {
                w = 0x80000000u;  // virtual prefix 0 before tile 0
            }
            unsigned isPre = __ballot_sync(0xffffffffu, (w & 0x80000000u) != 0u);
            if (isPre) {
                int pl = __ffs(isPre) - 1;
                unsigned contrib = (lane <= pl) ? (w & 0x3FFFFFFFu) : 0u;
                #pragma unroll
                for (int o = 16; o; o >>= 1) contrib += __shfl_down_sync(0xffffffffu, contrib, o);
                if (lane == 0) excl += contrib;
                break;
            } else {
                unsigned contrib = w & 0x3FFFFFFFu;
                #pragma unroll
                for (int o = 16; o; o >>= 1) contrib += __shfl_down_sync(0xffffffffu, contrib, o);
                if (lane == 0) excl += contrib;
                j -= 32;
            }
        }
        if (lane == 0) {
            s_excl = (int)excl;
            vst[tile] = 0x80000000u | (excl + (unsigned)agg);
            if (tile == nTiles - 1) {
                int tot = (int)(excl + (unsigned)agg);
                g_voxelNum = tot < MAXV ? tot : MAXV;
            }
        }
    }
    __syncthreads();
    int base = s_excl + thrExcl;

    // phase 3a: reps emit (incl. the output row); NO cnt store
    int running = 0;
    bool isNR[IPT];
    #pragma unroll
    for (int k = 0; k < IPT; k++) {
        int i = i0 + k;
        bool valid = (i < n) && (sidx[k] >= 0);
        isNR[k] = valid && !rep[k];
        if (valid && rep[k]) {
            int vid = base + running;
            running++;
            g_pvid[i] = PV_RESOLVED | vid;
            if (vid < MAXV) {
                int f = flat[k];
                g_coors4[vid] = make_int4(f % GZ, (f / GZ) % GY, f / (GZ * GY), 0);
                g_slots[vid * MAXP] = (unsigned)(n - i);  // rep key guards slot 0
                reinterpret_cast<float4*>(out)[vid * MAXP] = pts[i];  // slot 0 = rep, final
            }
        }
    }

    // phase 3b: non-rep append, ONE atomicAdd per warp (list order irrelevant:
    // ripple final-state is insertion-order independent)
    unsigned m[IPT];
    int warpTot = 0;
    #pragma unroll
    for (int k = 0; k < IPT; k++) {
        m[k] = __ballot_sync(0xffffffffu, isNR[k]);
        warpTot += __popc(m[k]);
    }
    if (warpTot) {
        int wb;
        if (lane == 0) wb = atomicAdd(&g_nrCount, warpTot);
        wb = __shfl_sync(0xffffffffu, wb, 0);
        int off = 0;
        #pragma unroll
        for (int k = 0; k < IPT; k++) {
            if (isNR[k]) {
                int pre = off + __popc(m[k] & ((1u << lane) - 1u));
                int i = i0 + k;
                g_nrList[wb + pre] =
                    ((unsigned long long)(unsigned)i << 21) | (unsigned)(n - key[k]);
            }
            off += __popc(m[k]);
        }
    }
}

// ---------------------------------------------------------------------------
// C: micro-kernel — non-rep inserts only (rep vid lookup + EXTRA count +
// deterministic atomicMax ripple; rep key in slot 0 pushes them to slot 1+).
// ---------------------------------------------------------------------------
__global__ void kC_nonrep(int n) {
    int total = g_nrCount;
    for (int j = blockIdx.x * BLK + threadIdx.x; j < total; j += NRB * BLK) {
        unsigned long long e = g_nrList[j];
        int i = (int)(e >> 21);
        int irep = (int)(e & KMASK);
        int vid = __ldcg(&g_pvid[irep]) & (PV_RESOLVED - 1);
        if (vid >= MAXV) continue;
        atomicAdd(&g_cnt[vid], 1);   // extras only; rep's 1 is implicit
        unsigned key = (unsigned)(n - i);
        unsigned* sl = &g_slots[(unsigned)vid * MAXP];
        for (int s = 0; s < MAXP; s++) {
            unsigned old = atomicMax(&sl[s], key);
            if (old < key) {
                if (old == 0u) break;  // landed in empty slot
                key = old;             // displaced occupant ripples right
            }
        }
    }
}

// ---------------------------------------------------------------------------
// D: split grid. Head: 4 voxels per warp emit. cnt = (vid<vn) + extras.
// cnt==1: 31 zero rows + slot0 reset, no slot reads. cnt>1: read keys, gather.
// Tail: htab stream-zero (one 16B store per thread) + status clear.
// Output layout: voxels[60000*32*4] | coors[60000*3] | npv[60000] | voxel_num[1]
// ---------------------------------------------------------------------------
__global__ void kD_emit(const float4* __restrict__ pts, float* __restrict__ out,
                        int n, int nTiles) {
    int b = blockIdx.x;
    if (b < VOXBLKS) {
        int lane = threadIdx.x & 31;
        int vbase = ((b * BLK + threadIdx.x) >> 5) * VPW;
        const int OC = SLOTS * 4;
        const int ON = OC + MAXV * 3;
        int vn = g_voxelNum;

        int c = 0;
        if (lane < VPW) {
            int ce = g_cnt[vbase + lane];
            if (ce) g_cnt[vbase + lane] = 0;   // reset only the ~6.5k touched cells
            c = ((vbase + lane) < vn ? 1 : 0) + ce;
            out[ON + vbase + lane] = (float)(c > MAXP ? MAXP : c);
        }
        if (lane < 3 * VPW) {
            int vv = vbase + lane / 3;
            int coor = reinterpret_cast<const int*>(g_coors4)[vv * 4 + (lane % 3)];
            out[OC + vbase * 3 + lane] = (vv < vn) ? (float)coor : 0.f;
        }
        if (b == 0 && threadIdx.x == 0) {
            out[ON + MAXV] = (float)vn;
            g_nrCount = 0;
        }

        const float4 zero = make_float4(0.f, 0.f, 0.f, 0.f);
        #pragma unroll
        for (int j = 0; j < VPW; j++) {
            int cj = __shfl_sync(0xffffffffu, c, j);
            int row = (vbase + j) * MAXP + lane;
            if (cj <= 1) {
                if (lane || cj == 0) reinterpret_cast<float4*>(out)[row] = zero;
                if (cj == 1 && lane == 0) g_slots[row] = 0;
            } else {
                unsigned k = g_slots[row];
                g_slots[row] = 0;
                if (lane)  // lane 0's row written by kB (slot 0 == rep, final)
                    reinterpret_cast<float4*>(out)[row] = k ? pts[n - (int)k] : zero;
            }
        }
    } else {
        int j = (b - VOXBLKS) * BLK + threadIdx.x;
        if (j < (int)(HSIZE / 2)) {
            // coalesced 16B stores: zero two hash entries per thread
            reinterpret_cast<ulonglong2*>(g_htab)[j] = make_ulonglong2(0ull, 0ull);
        } else {
            int j2 = j - (int)(HSIZE / 2);
            if (j2 < nTiles) g_status[j2] = 0;
        }
    }
}

extern "C" void kernel_launch(void* const* d_in, const int* in_sizes, int n_in,
                              void* d_out, int out_size) {
    const float4* pts = (const float4*)d_in[0];
    int n = in_sizes[0] / 4;
    float* out = (float*)d_out;
    int nT = (n + TILE - 1) / TILE;

    kA_claim<<<nT, BLK>>>(pts, n);
    kB_scan_assign<<<nT, BLK>>>(pts, out, n, nT);
    kC_nonrep<<<NRB, BLK>>>(n);
    int tailBlocks = ((int)(HSIZE / 2) + nT + BLK - 1) / BLK;
    kD_emit<<<VOXBLKS + tailBlocks, BLK>>>(pts, out, n, nT);
}